// round 14
// baseline (speedup 1.0000x reference)
#include <cuda_runtime.h>

#define NT        512
#define MAX_LOG2N 14

// K spectra: up to 8M complex = 64 MB (covers H * NFFT <= 8M, e.g. 256*16384=4M).
__device__ float2 g_Kf[8u * 1024u * 1024u];
// Root twiddles tw[k] = exp(-2*pi*i*k/NFFT), k < NFFT/2 (<= 8192 -> 64 KB).
__device__ float2 g_tw[1 << (MAX_LOG2N - 1)];

__global__ void twiddle_kernel(int nfft) {
    const int half = nfft >> 1;
    const float w = -6.283185307179586f / (float)nfft;
    for (int k = blockIdx.x * blockDim.x + threadIdx.x; k < half;
         k += gridDim.x * blockDim.x) {
        float s, c;
        sincosf(w * (float)k, &s, &c);
        g_tw[k] = make_float2(c, s);
    }
}

template<int LOG2N>
__device__ __forceinline__ int bitrev(int x) {
    return (int)(__brev((unsigned)x) >> (32 - LOG2N));
}

// Forward radix-2 DIT: input bit-reversed, output natural order.
template<int LOG2N>
__device__ void fft_dit(float* __restrict__ re, float* __restrict__ im) {
    const int N = 1 << LOG2N;
    for (int s = 1; s <= LOG2N; s++) {
        const int half = 1 << (s - 1);
        const int tsh  = LOG2N - s;
        for (int j = threadIdx.x; j < N / 2; j += NT) {
            const int k  = j & (half - 1);
            const int i0 = ((j >> (s - 1)) << s) + k;
            const int i1 = i0 + half;
            const float2 w = g_tw[k << tsh];
            const float br = re[i1], bi = im[i1];
            const float tr = w.x * br - w.y * bi;
            const float tq = w.x * bi + w.y * br;
            const float ar = re[i0], ai = im[i0];
            re[i1] = ar - tr;  im[i1] = ai - tq;
            re[i0] = ar + tr;  im[i0] = ai + tq;
        }
        __syncthreads();
    }
}

// Inverse radix-2 DIF (conjugate twiddles): input natural, output bit-reversed.
template<int LOG2N>
__device__ void ifft_dif(float* __restrict__ re, float* __restrict__ im) {
    const int N = 1 << LOG2N;
    for (int s = LOG2N; s >= 1; s--) {
        const int half = 1 << (s - 1);
        const int tsh  = LOG2N - s;
        for (int j = threadIdx.x; j < N / 2; j += NT) {
            const int k  = j & (half - 1);
            const int i0 = ((j >> (s - 1)) << s) + k;
            const int i1 = i0 + half;
            const float2 w = g_tw[k << tsh];   // conj applied in-line
            const float ar = re[i0], ai = im[i0];
            const float br = re[i1], bi = im[i1];
            re[i0] = ar + br;  im[i0] = ai + bi;
            const float dr = ar - br, di = ai - bi;
            re[i1] = w.x * dr + w.y * di;
            im[i1] = w.x * di - w.y * dr;
        }
        __syncthreads();
    }
}

// Kernel A: forward FFT of each K row -> g_Kf (natural order).
template<int LOG2N>
__global__ __launch_bounds__(NT, 1)
void kfft_kernel(const float* __restrict__ Kmat, int L) {
    const int N = 1 << LOG2N;
    extern __shared__ float sm[];
    float* re = sm;
    float* im = sm + N;

    const int h = blockIdx.x;
    const float* krow = Kmat + (long)h * L;
    for (int t = threadIdx.x; t < N; t += NT) {
        const int r = bitrev<LOG2N>(t);
        re[r] = (t < L) ? krow[t] : 0.0f;
        im[r] = 0.0f;
    }
    __syncthreads();

    fft_dit<LOG2N>(re, im);

    float2* dst = g_Kf + (long)h * N;
    for (int t = threadIdx.x; t < N; t += NT)
        dst[t] = make_float2(re[t], im[t]);
}

// Kernel B: complex-packed pair of batch rows per CTA.
//   z = u[b0] + i*u[b1] (both real) -> ifft(fft(z) * Kf) = y0 + i*y1,
// since the FFT is linear and conv(real, real) is real. Skip D*u fused at
// the store. Output layout dispatched at runtime on complex_out:
//   complex_out=1: interleaved (re, im) float pairs, im = 0 (true result is real)
//   complex_out=0: real float per element (out_size == B*H*L)
template<int LOG2N>
__global__ __launch_bounds__(NT, 1)
void conv_kernel(const float* __restrict__ u, const float* __restrict__ D,
                 float* __restrict__ out, int L, int H, int B, int complex_out) {
    const int N = 1 << LOG2N;
    extern __shared__ float sm[];
    float* re = sm;
    float* im = sm + N;

    const int h  = blockIdx.x;
    const int b0 = 2 * blockIdx.y;
    const bool has_b1 = (b0 + 1) < B;
    const int b1 = has_b1 ? b0 + 1 : b0;
    const long row0 = ((long)b0 * H + h) * L;
    const long row1 = ((long)b1 * H + h) * L;
    const float* u0 = u + row0;
    const float* u1 = u + row1;

    for (int t = threadIdx.x; t < N; t += NT) {
        const int r = bitrev<LOG2N>(t);
        if (t < L) { re[r] = u0[t]; im[r] = u1[t]; }
        else       { re[r] = 0.0f;  im[r] = 0.0f;  }
    }
    __syncthreads();

    fft_dit<LOG2N>(re, im);

    // Pointwise multiply packed spectrum with K spectrum, fold in 1/N.
    const float2* __restrict__ kf = g_Kf + (long)h * N;
    const float invN = 1.0f / (float)N;
    for (int t = threadIdx.x; t < N; t += NT) {
        const float2 kv = kf[t];
        const float ar = re[t], ai = im[t];
        re[t] = (ar * kv.x - ai * kv.y) * invN;
        im[t] = (ar * kv.y + ai * kv.x) * invN;
    }
    __syncthreads();

    ifft_dif<LOG2N>(re, im);
    // Results bit-reversed: y0[t] = re[bitrev(t)], y1[t] = im[bitrev(t)].

    const float d = D[h];
    if (complex_out) {
        float2* o0 = (float2*)out + row0;
        float2* o1 = (float2*)out + row1;
        for (int t = threadIdx.x; t < L; t += NT) {
            const int r = bitrev<LOG2N>(t);
            o0[t] = make_float2(re[r] + d * u0[t], 0.0f);
            if (has_b1)
                o1[t] = make_float2(im[r] + d * u1[t], 0.0f);
        }
    } else {
        float* o0 = out + row0;
        float* o1 = out + row1;
        for (int t = threadIdx.x; t < L; t += NT) {
            const int r = bitrev<LOG2N>(t);
            o0[t] = re[r] + d * u0[t];
            if (has_b1)
                o1[t] = im[r] + d * u1[t];
        }
    }
}

template<int LOG2N>
static void run(const float* u, const float* K, const float* D, float* out,
                int L, int H, int B, int complex_out) {
    const size_t smem = (size_t)(2u << LOG2N) * sizeof(float);  // 2*NFFT floats
    cudaFuncSetAttribute(kfft_kernel<LOG2N>,
                         cudaFuncAttributeMaxDynamicSharedMemorySize, (int)smem);
    cudaFuncSetAttribute(conv_kernel<LOG2N>,
                         cudaFuncAttributeMaxDynamicSharedMemorySize, (int)smem);
    kfft_kernel<LOG2N><<<H, NT, smem>>>(K, L);
    conv_kernel<LOG2N><<<dim3(H, (B + 1) / 2), NT, smem>>>(u, D, out, L, H, B,
                                                           complex_out);
}

extern "C" void kernel_launch(void* const* d_in, const int* in_sizes, int n_in,
                              void* d_out, int out_size) {
    // Identify inputs by relative size: u (largest), D (smallest), K (middle).
    int iu = 0, iK = 1, iD = 2;
    if (n_in >= 3) {
        iu = 0; iD = 0;
        for (int i = 1; i < 3; i++) {
            if (in_sizes[i] > in_sizes[iu]) iu = i;
            if (in_sizes[i] < in_sizes[iD]) iD = i;
        }
        if (iu == iD) { iu = 0; iK = 1; iD = 2; }
        else          { iK = 3 - iu - iD; }
    }
    const float* u = (const float*)d_in[iu];
    const float* K = (const float*)d_in[iK];
    const float* D = (const float*)d_in[iD];
    float* out = (float*)d_out;

    // Derive shapes at runtime.
    const int H = in_sizes[iD];
    const int L = (H > 0) ? in_sizes[iK] / H : 0;
    const int B = (in_sizes[iK] > 0) ? (int)((long)in_sizes[iu] / in_sizes[iK]) : 0;
    if (H <= 0 || L <= 0 || B <= 0) return;

    // Output layout: the harness dtype system has no complex64. If out_size
    // equals 2*B*H*L, the complex output is stored as interleaved float32
    // pairs; if it equals B*H*L, only the real part is stored (the true
    // convolution result is real). Never write past out_size floats.
    const long nelem = (long)B * H * L;
    const int complex_out = (out_size >= 2 * nelem) ? 1 : 0;

    int log2n = 1;
    while ((1 << log2n) < 2 * L - 1) log2n++;
    if (log2n > MAX_LOG2N) log2n = MAX_LOG2N;
    if (log2n < 6) log2n = 6;

    twiddle_kernel<<<64, 256>>>(1 << log2n);

    switch (log2n) {
        case 6:  run<6> (u, K, D, out, L, H, B, complex_out); break;
        case 7:  run<7> (u, K, D, out, L, H, B, complex_out); break;
        case 8:  run<8> (u, K, D, out, L, H, B, complex_out); break;
        case 9:  run<9> (u, K, D, out, L, H, B, complex_out); break;
        case 10: run<10>(u, K, D, out, L, H, B, complex_out); break;
        case 11: run<11>(u, K, D, out, L, H, B, complex_out); break;
        case 12: run<12>(u, K, D, out, L, H, B, complex_out); break;
        case 13: run<13>(u, K, D, out, L, H, B, complex_out); break;
        default: run<14>(u, K, D, out, L, H, B, complex_out); break;
    }
}

// round 15
// speedup vs baseline: 1.5053x; 1.5053x over previous
#include <cuda_runtime.h>

#define NT        512
#define MAX_LOG2N 14

// K spectra: up to 8M complex = 64 MB (covers H * NFFT <= 8M, e.g. 256*16384=4M).
__device__ float2 g_Kf[8u * 1024u * 1024u];

template<int LOG2N>
__device__ __forceinline__ int bitrev(int x) {
    return (int)(__brev((unsigned)x) >> (32 - LOG2N));
}

__device__ __forceinline__ float2 cmul(float2 a, float2 b) {
    return make_float2(a.x * b.x - a.y * b.y, a.x * b.y + a.y * b.x);
}
// conj(w) * d
__device__ __forceinline__ float2 cmulc(float2 w, float2 d) {
    return make_float2(w.x * d.x + w.y * d.y, w.x * d.y - w.y * d.x);
}
__device__ __forceinline__ float2 cadd(float2 a, float2 b) {
    return make_float2(a.x + b.x, a.y + b.y);
}
__device__ __forceinline__ float2 csub(float2 a, float2 b) {
    return make_float2(a.x - b.x, a.y - b.y);
}

// Twiddles in smem: tw[k] = exp(-2*pi*i*k/N), k < N/2. ~16 sincosf/thread, once per CTA.
template<int LOG2N>
__device__ void make_tw(float2* tw) {
    const int N = 1 << LOG2N;
    const float w = -6.283185307179586f / (float)N;
    for (int k = threadIdx.x; k < N / 2; k += NT) {
        float s, c;
        sincosf(w * (float)k, &s, &c);
        tw[k] = make_float2(c, s);
    }
}

// Forward DIT, radix-2 stages fused in pairs (radix-4 smem traffic).
// Input bit-reversed, output natural.
template<int LOG2N>
__device__ void fft_fwd(float2* __restrict__ z, const float2* __restrict__ tw) {
    const int N = 1 << LOG2N;
    int s = 1;
    if (LOG2N & 1) {           // leftover single radix-2 stage (tw[0] = 1)
        for (int j = threadIdx.x; j < N / 2; j += NT) {
            const int i0 = 2 * j;
            const float2 a = z[i0], b = z[i0 + 1];
            z[i0] = cadd(a, b);
            z[i0 + 1] = csub(a, b);
        }
        __syncthreads();
        s = 2;
    }
    for (; s < LOG2N; s += 2) {            // pair (s, s+1)
        const int h   = 1 << (s - 1);
        const int tsh = LOG2N - s;
        #pragma unroll 4
        for (int j = threadIdx.x; j < N / 4; j += NT) {
            const int k  = j & (h - 1);
            const int i0 = ((j >> (s - 1)) << (s + 1)) + k;
            float2 z0 = z[i0], z1 = z[i0 + h], z2 = z[i0 + 2 * h], z3 = z[i0 + 3 * h];
            const float2 w1 = tw[k << tsh];
            const float2 wa = tw[k << (tsh - 1)];
            const float2 wb = tw[(k + h) << (tsh - 1)];
            float2 t;
            t = cmul(w1, z1); const float2 a0 = cadd(z0, t), a1 = csub(z0, t);
            t = cmul(w1, z3); const float2 a2 = cadd(z2, t), a3 = csub(z2, t);
            t = cmul(wa, a2); z[i0]         = cadd(a0, t); z[i0 + 2 * h] = csub(a0, t);
            t = cmul(wb, a3); z[i0 + h]     = cadd(a1, t); z[i0 + 3 * h] = csub(a1, t);
        }
        __syncthreads();
    }
}

// Inverse DIF (conjugate twiddles), stage pairs. Input natural, output bit-reversed.
// If MUL: fuse pointwise z *= kf * invN into the first pair's loads.
template<int LOG2N, bool MUL>
__device__ void fft_inv(float2* __restrict__ z, const float2* __restrict__ tw,
                        const float2* __restrict__ kf, float invN) {
    const int N = 1 << LOG2N;
    int s = LOG2N;
    bool first = true;
    for (; s >= 2; s -= 2) {               // pair (s, s-1)
        const int sl   = s - 1;
        const int hl   = 1 << (sl - 1);
        const int tshh = LOG2N - s;
        const int tshl = tshh + 1;
        #pragma unroll 4
        for (int j = threadIdx.x; j < N / 4; j += NT) {
            const int k  = j & (hl - 1);
            const int i0 = ((j >> (sl - 1)) << (sl + 1)) + k;
            float2 z0 = z[i0], z1 = z[i0 + hl], z2 = z[i0 + 2 * hl], z3 = z[i0 + 3 * hl];
            if (MUL && first) {
                float2 m;
                m = cmul(z0, kf[i0]);          z0 = make_float2(m.x * invN, m.y * invN);
                m = cmul(z1, kf[i0 + hl]);     z1 = make_float2(m.x * invN, m.y * invN);
                m = cmul(z2, kf[i0 + 2 * hl]); z2 = make_float2(m.x * invN, m.y * invN);
                m = cmul(z3, kf[i0 + 3 * hl]); z3 = make_float2(m.x * invN, m.y * invN);
            }
            const float2 wa = tw[k << tshh];
            const float2 wb = tw[(k + hl) << tshh];
            const float2 w1 = tw[k << tshl];
            const float2 a0 = cadd(z0, z2), a2 = cmulc(wa, csub(z0, z2));
            const float2 a1 = cadd(z1, z3), a3 = cmulc(wb, csub(z1, z3));
            z[i0]          = cadd(a0, a1);
            z[i0 + hl]     = cmulc(w1, csub(a0, a1));
            z[i0 + 2 * hl] = cadd(a2, a3);
            z[i0 + 3 * hl] = cmulc(w1, csub(a2, a3));
        }
        __syncthreads();
        first = false;
    }
    if (s == 1) {                          // leftover single radix-2 stage
        for (int j = threadIdx.x; j < N / 2; j += NT) {
            const int i0 = 2 * j;
            const float2 a = z[i0], b = z[i0 + 1];
            z[i0] = cadd(a, b);
            z[i0 + 1] = csub(a, b);
        }
        __syncthreads();
    }
}

// Kernel A: forward FFT of each K row -> g_Kf (natural order).
template<int LOG2N>
__global__ __launch_bounds__(NT, 1)
void kfft_kernel(const float* __restrict__ Kmat, int L) {
    const int N = 1 << LOG2N;
    extern __shared__ float2 sm[];
    float2* z  = sm;           // N
    float2* tw = sm + N;       // N/2

    make_tw<LOG2N>(tw);

    const int h = blockIdx.x;
    const float* krow = Kmat + (long)h * L;
    for (int t = threadIdx.x; t < N; t += NT) {
        const int r = bitrev<LOG2N>(t);
        z[r] = make_float2((t < L) ? krow[t] : 0.0f, 0.0f);
    }
    __syncthreads();

    fft_fwd<LOG2N>(z, tw);

    float2* dst = g_Kf + (long)h * N;
    for (int t = threadIdx.x; t < N; t += NT)
        dst[t] = z[t];
}

// Kernel B: complex-packed pair of batch rows per CTA.
//   z = u[b0] + i*u[b1] (real rows) -> ifft(fft(z) * Kf) = y0 + i*y1.
// Skip D*u fused at store. Output layout dispatched on complex_out.
template<int LOG2N>
__global__ __launch_bounds__(NT, 1)
void conv_kernel(const float* __restrict__ u, const float* __restrict__ D,
                 float* __restrict__ out, int L, int H, int B, int complex_out) {
    const int N = 1 << LOG2N;
    extern __shared__ float2 sm[];
    float2* z  = sm;
    float2* tw = sm + N;

    make_tw<LOG2N>(tw);

    const int h  = blockIdx.x;
    const int b0 = 2 * blockIdx.y;
    const bool has_b1 = (b0 + 1) < B;
    const int b1 = has_b1 ? b0 + 1 : b0;
    const long row0 = ((long)b0 * H + h) * L;
    const long row1 = ((long)b1 * H + h) * L;
    const float* u0 = u + row0;
    const float* u1 = u + row1;

    for (int t = threadIdx.x; t < N; t += NT) {
        const int r = bitrev<LOG2N>(t);
        z[r] = (t < L) ? make_float2(u0[t], u1[t]) : make_float2(0.0f, 0.0f);
    }
    __syncthreads();

    fft_fwd<LOG2N>(z, tw);

    // Inverse with fused pointwise multiply by K spectrum * (1/N).
    const float2* __restrict__ kf = g_Kf + (long)h * N;
    fft_inv<LOG2N, true>(z, tw, kf, 1.0f / (float)N);
    // Results bit-reversed: y0[t] = z[bitrev(t)].x, y1[t] = z[bitrev(t)].y.

    const float d = D[h];
    if (complex_out) {
        float2* o0 = (float2*)out + row0;
        float2* o1 = (float2*)out + row1;
        for (int t = threadIdx.x; t < L; t += NT) {
            const float2 y = z[bitrev<LOG2N>(t)];
            o0[t] = make_float2(y.x + d * u0[t], 0.0f);
            if (has_b1)
                o1[t] = make_float2(y.y + d * u1[t], 0.0f);
        }
    } else {
        float* o0 = out + row0;
        float* o1 = out + row1;
        for (int t = threadIdx.x; t < L; t += NT) {
            const float2 y = z[bitrev<LOG2N>(t)];
            o0[t] = y.x + d * u0[t];
            if (has_b1)
                o1[t] = y.y + d * u1[t];
        }
    }
}

template<int LOG2N>
static void run(const float* u, const float* K, const float* D, float* out,
                int L, int H, int B, int complex_out) {
    const size_t smem = (size_t)(3u << (LOG2N - 1)) * sizeof(float2);  // 12*N bytes
    cudaFuncSetAttribute(kfft_kernel<LOG2N>,
                         cudaFuncAttributeMaxDynamicSharedMemorySize, (int)smem);
    cudaFuncSetAttribute(conv_kernel<LOG2N>,
                         cudaFuncAttributeMaxDynamicSharedMemorySize, (int)smem);
    kfft_kernel<LOG2N><<<H, NT, smem>>>(K, L);
    conv_kernel<LOG2N><<<dim3(H, (B + 1) / 2), NT, smem>>>(u, D, out, L, H, B,
                                                           complex_out);
}

extern "C" void kernel_launch(void* const* d_in, const int* in_sizes, int n_in,
                              void* d_out, int out_size) {
    // Identify inputs by relative size: u (largest), D (smallest), K (middle).
    int iu = 0, iK = 1, iD = 2;
    if (n_in >= 3) {
        iu = 0; iD = 0;
        for (int i = 1; i < 3; i++) {
            if (in_sizes[i] > in_sizes[iu]) iu = i;
            if (in_sizes[i] < in_sizes[iD]) iD = i;
        }
        if (iu == iD) { iu = 0; iK = 1; iD = 2; }
        else          { iK = 3 - iu - iD; }
    }
    const float* u = (const float*)d_in[iu];
    const float* K = (const float*)d_in[iK];
    const float* D = (const float*)d_in[iD];
    float* out = (float*)d_out;

    // Derive shapes at runtime.
    const int H = in_sizes[iD];
    const int L = (H > 0) ? in_sizes[iK] / H : 0;
    const int B = (in_sizes[iK] > 0) ? (int)((long)in_sizes[iu] / in_sizes[iK]) : 0;
    if (H <= 0 || L <= 0 || B <= 0) return;

    // Output layout: complex64 stored as interleaved float pairs (out_size ==
    // 2*B*H*L) vs real-only float (out_size == B*H*L). Never exceed out_size.
    const long nelem = (long)B * H * L;
    const int complex_out = (out_size >= 2 * nelem) ? 1 : 0;

    int log2n = 1;
    while ((1 << log2n) < 2 * L - 1) log2n++;
    if (log2n > MAX_LOG2N) log2n = MAX_LOG2N;
    if (log2n < 6) log2n = 6;

    switch (log2n) {
        case 6:  run<6> (u, K, D, out, L, H, B, complex_out); break;
        case 7:  run<7> (u, K, D, out, L, H, B, complex_out); break;
        case 8:  run<8> (u, K, D, out, L, H, B, complex_out); break;
        case 9:  run<9> (u, K, D, out, L, H, B, complex_out); break;
        case 10: run<10>(u, K, D, out, L, H, B, complex_out); break;
        case 11: run<11>(u, K, D, out, L, H, B, complex_out); break;
        case 12: run<12>(u, K, D, out, L, H, B, complex_out); break;
        case 13: run<13>(u, K, D, out, L, H, B, complex_out); break;
        default: run<14>(u, K, D, out, L, H, B, complex_out); break;
    }
}